// round 13
// baseline (speedup 1.0000x reference)
#include <cuda_runtime.h>
#include <cstdint>

#define NUM_C   64
#define FD      128
#define FD4     32
#define BLK     256
#define NWARP   8
#define GRID    296          // 2 blocks per SM, exactly one wave
#define PER_CAP 3456         // ceil(1e6/296)=3379
#define T       64           // rows per tile (32KB f32)
#define N_PAIRS 2016

__device__ float        g_sums[NUM_C * FD];
__device__ int          g_counts[NUM_C];
__device__ float        g_sumsq;
__device__ unsigned int g_ticket;

__global__ void __launch_bounds__(BLK, 2)
fused_k(const float* __restrict__ feat, const int* __restrict__ tgt, int B,
        float* __restrict__ out)
{
    __shared__ __align__(16) float tile[T * FD];        // 32KB; aliased as cent[] in epilogue
    __shared__ __align__(4)  unsigned char stgt[PER_CAP];
    __shared__ int   hist[NUM_C];
    __shared__ float s_red[NWARP], s_sq[NWARP], s_hred[NWARP];
    __shared__ int   s_last;

    float4* tile4 = (float4*)tile;

    const int tid = threadIdx.x;
    const int w = tid >> 5, l = tid & 31;

    const int per = (B + GRID - 1) / GRID;
    const int r0  = blockIdx.x * per;
    int n = B - r0; if (n > per) n = per; if (n < 0) n = 0;

    if (tid < NUM_C) hist[tid] = 0;
    __syncthreads();

    // ---- phase A: targets -> smem, histogram ----
    for (int i = tid; i < n; i += BLK) {
        int t = tgt[r0 + i];
        stgt[i] = (unsigned char)t;
        atomicAdd(&hist[t], 1);
    }
    __syncthreads();

    // ---- phase B: sequential tile streaming + register-resident class sums ----
    // warp w owns classes [8w, 8w+8); lane l owns dims [4l, 4l+4)
    float4 a0 = {0,0,0,0}, a1 = {0,0,0,0}, a2 = {0,0,0,0}, a3 = {0,0,0,0};
    float4 a4 = {0,0,0,0}, a5 = {0,0,0,0}, a6 = {0,0,0,0}, a7 = {0,0,0,0};
    float sq0 = 0.f, sq1 = 0.f;

    const float4* fbase = (const float4*)feat + (size_t)r0 * FD4;
    const int lim4 = n * FD4;
    const int G = (n + T - 1) / T;

    float4 st[8];                                       // staging: 8 float4/thread = one tile
    const float4 Z = {0,0,0,0};
#pragma unroll
    for (int i = 0; i < 8; i++) {                       // prolog: load tile 0 (sequential)
        int idx = tid + i * BLK;
        st[i] = (idx < lim4) ? fbase[idx] : Z;
    }

    for (int g = 0; g < G; g++) {
        // deposit tile + fp32 sumsq
#pragma unroll
        for (int i = 0; i < 8; i++) {
            tile4[tid + i * BLK] = st[i];
            float4 x = st[i];
            if (i & 1) sq1 = fmaf(x.x, x.x, fmaf(x.y, x.y, fmaf(x.z, x.z, fmaf(x.w, x.w, sq1))));
            else       sq0 = fmaf(x.x, x.x, fmaf(x.y, x.y, fmaf(x.z, x.z, fmaf(x.w, x.w, sq0))));
        }
        __syncthreads();                                // tile visible to all

        // prefetch next tile NOW (sequential LDG overlaps the scan below)
        if (g + 1 < G) {
            const int b4 = (g + 1) * (T * FD4);
#pragma unroll
            for (int i = 0; i < 8; i++) {
                int idx = b4 + tid + i * BLK;
                st[i] = (idx < lim4) ? fbase[idx] : Z;
            }
        }

        // scan this tile's targets; accumulate owned rows from smem
        const int kmax = min(T, n - g * T);
        const unsigned char* tg = &stgt[g * T];
        int k = 0;
        for (; k + 4 <= kmax; k += 4) {
            unsigned int tw = *(const unsigned int*)(tg + k);   // 4 targets, one LDS
#pragma unroll
            for (int u = 0; u < 4; u++) {
                int c = (tw >> (u * 8)) & 0xff;
                if ((c >> 3) == w) {                    // warp-uniform ownership test
                    float4 x = tile4[(k + u) * FD4 + l];
                    switch (c & 7) {
                        case 0: a0.x+=x.x; a0.y+=x.y; a0.z+=x.z; a0.w+=x.w; break;
                        case 1: a1.x+=x.x; a1.y+=x.y; a1.z+=x.z; a1.w+=x.w; break;
                        case 2: a2.x+=x.x; a2.y+=x.y; a2.z+=x.z; a2.w+=x.w; break;
                        case 3: a3.x+=x.x; a3.y+=x.y; a3.z+=x.z; a3.w+=x.w; break;
                        case 4: a4.x+=x.x; a4.y+=x.y; a4.z+=x.z; a4.w+=x.w; break;
                        case 5: a5.x+=x.x; a5.y+=x.y; a5.z+=x.z; a5.w+=x.w; break;
                        case 6: a6.x+=x.x; a6.y+=x.y; a6.z+=x.z; a6.w+=x.w; break;
                        case 7: a7.x+=x.x; a7.y+=x.y; a7.z+=x.z; a7.w+=x.w; break;
                    }
                }
            }
        }
        for (; k < kmax; k++) {                         // tail (<4 rows)
            int c = tg[k];
            if ((c >> 3) == w) {
                float4 x = tile4[k * FD4 + l];
                switch (c & 7) {
                    case 0: a0.x+=x.x; a0.y+=x.y; a0.z+=x.z; a0.w+=x.w; break;
                    case 1: a1.x+=x.x; a1.y+=x.y; a1.z+=x.z; a1.w+=x.w; break;
                    case 2: a2.x+=x.x; a2.y+=x.y; a2.z+=x.z; a2.w+=x.w; break;
                    case 3: a3.x+=x.x; a3.y+=x.y; a3.z+=x.z; a3.w+=x.w; break;
                    case 4: a4.x+=x.x; a4.y+=x.y; a4.z+=x.z; a4.w+=x.w; break;
                    case 5: a5.x+=x.x; a5.y+=x.y; a5.z+=x.z; a5.w+=x.w; break;
                    case 6: a6.x+=x.x; a6.y+=x.y; a6.z+=x.z; a6.w+=x.w; break;
                    case 7: a7.x+=x.x; a7.y+=x.y; a7.z+=x.z; a7.w+=x.w; break;
                }
            }
        }
        __syncthreads();                                // scan done before tile overwrite
    }

    // ---- flush register accumulators: one atomic add per (class, dim) per block ----
    {
        float* gp = g_sums + (w * 8) * FD + (l << 2);
#define FLUSH(A) { atomicAdd(gp+0,(A).x); atomicAdd(gp+1,(A).y); \
                   atomicAdd(gp+2,(A).z); atomicAdd(gp+3,(A).w); gp += FD; }
        FLUSH(a0) FLUSH(a1) FLUSH(a2) FLUSH(a3)
        FLUSH(a4) FLUSH(a5) FLUSH(a6) FLUSH(a7)
#undef FLUSH
    }
    if (tid < NUM_C) atomicAdd(&g_counts[tid], hist[tid]);

    float sq = sq0 + sq1;
#pragma unroll
    for (int o = 16; o > 0; o >>= 1) sq += __shfl_down_sync(0xffffffffu, sq, o);
    if (l == 0) s_sq[w] = sq;
    __syncthreads();
    if (tid == 0) {
        float t = 0.f;
#pragma unroll
        for (int k = 0; k < NWARP; k++) t += s_sq[k];
        atomicAdd(&g_sumsq, t);
    }

    __threadfence();
    __syncthreads();
    if (tid == 0) {
        unsigned int tk = atomicAdd(&g_ticket, 1u);
        s_last = (tk == gridDim.x - 1);
    }
    __syncthreads();
    if (!s_last) return;

    // ================= last block: epilogue (cent aliases tile) =================
    __threadfence();
    float* cent = tile;

    float ipart = 0.f;
    for (int i = tid; i < NUM_C * FD; i += BLK) {
        const int c = i >> 7;
        float cntc = fmaxf((float)g_counts[c], 1.0f);
        float s  = g_sums[i];
        float ce = s / cntc;
        cent[i]  = ce;
        ipart   += s * ce;                 // sum_c cnt_c * ||cent_c||^2
        g_sums[i] = 0.f;                   // reset for next graph replay
    }
    float ssq = 0.f;
    if (tid == 0) { ssq = g_sumsq; g_sumsq = 0.f; g_ticket = 0u; }
    __syncthreads();
    if (tid < NUM_C) g_counts[tid] = 0;

#pragma unroll
    for (int o = 16; o > 0; o >>= 1) ipart += __shfl_down_sync(0xffffffffu, ipart, o);
    if (l == 0) s_red[w] = ipart;
    __syncthreads();

    const float4* c4 = (const float4*)cent;
    float hsum = 0.f;
    for (int i = w; i < NUM_C - 1; i += NWARP) {
        float4 a = c4[i * FD4 + l];
        for (int j = i + 1; j < NUM_C; j++) {
            float4 b = c4[j * FD4 + l];
            float dx = a.x - b.x, dy = a.y - b.y, dz = a.z - b.z, dw = a.w - b.w;
            float d2 = dx * dx + dy * dy + dz * dz + dw * dw;
#pragma unroll
            for (int o = 16; o > 0; o >>= 1) d2 += __shfl_down_sync(0xffffffffu, d2, o);
            if (l == 0) {
                float wt = (i == 1 && j == 2) ? 2.0f : 1.0f;
                hsum += wt * fmaxf(2.0f - d2, 0.0f);     // MARGIN = 2
            }
        }
    }
    if (l == 0) s_hred[w] = hsum;
    __syncthreads();

    if (tid == 0) {
        float isum = 0.f, hs = 0.f;
#pragma unroll
        for (int k = 0; k < NWARP; k++) { isum += s_red[k]; hs += s_hred[k]; }
        out[0] = (ssq - isum) / (float)B + hs / (float)N_PAIRS;
    }
}

extern "C" void kernel_launch(void* const* d_in, const int* in_sizes, int n_in,
                              void* d_out, int out_size) {
    const float* feat = (const float*)d_in[0];
    const int*   tgt  = (const int*)d_in[1];
    const int B = in_sizes[1];
    fused_k<<<GRID, BLK>>>(feat, tgt, B, (float*)d_out);
}

// round 16
// speedup vs baseline: 1.5036x; 1.5036x over previous
#include <cuda_runtime.h>
#include <cstdint>

#define NUM_C   64
#define FD      128
#define FD4     32
#define BLK     256
#define NWARP   8
#define GRID    296          // 2 blocks/SM, one wave
#define PER_CAP 3392         // 53 tiles * 64; per-block rows = ceil(1e6/296) = 3379
#define NT      53           // tiles per block
#define T       64           // rows per tile (32KB fp32)
#define NKEY    (NT * NWARP) // 424 buckets
#define N_PAIRS 2016

// dynamic smem: tile (32KB, aliased as cent) | scomb | stgt
#define TILE_OFF 0
#define SCOMB_OFF 32768
#define STGT_OFF  (SCOMB_OFF + PER_CAP * 4)
#define SMEM_DYN  (STGT_OFF + PER_CAP)

__device__ float        g_sums[NUM_C * FD];
__device__ int          g_counts[NUM_C];
__device__ float        g_sumsq;
__device__ unsigned int g_ticket;

__global__ void __launch_bounds__(BLK, 2)
fused_k(const float* __restrict__ feat, const int* __restrict__ tgt, int B,
        float* __restrict__ out)
{
    extern __shared__ __align__(16) char dsm[];
    float*         tile  = (float*)(dsm + TILE_OFF);
    float4*        tile4 = (float4*)tile;
    unsigned int*  scomb = (unsigned int*)(dsm + SCOMB_OFF);  // (class<<16)|local_rowid
    unsigned char* stgt  = (unsigned char*)(dsm + STGT_OFF);

    __shared__ int   s[512];          // bucket counts -> inclusive prefix
    __shared__ int   cur[NKEY];
    __shared__ int   hist[NUM_C];
    __shared__ float s_sq[NWARP], s_red[NWARP], s_hred[NWARP];
    __shared__ int   s_last;

    const int tid = threadIdx.x;
    const int w = tid >> 5, l = tid & 31;

    const int per = (B + GRID - 1) / GRID;
    const int r0  = blockIdx.x * per;
    int n = B - r0; if (n > per) n = per; if (n < 0) n = 0;
    const int NTa = (n + T - 1) / T;

    if (tid < NUM_C) hist[tid] = 0;
    s[tid] = 0; s[tid + 256] = 0;
    __syncthreads();

    // ---- phase A: targets -> smem, histogram + (tile,warp) bucket counts ----
    for (int i = tid; i < n; i += BLK) {
        int t = tgt[r0 + i];
        stgt[i] = (unsigned char)t;
        atomicAdd(&hist[t], 1);
        atomicAdd(&s[(i >> 6) * NWARP + (t >> 3)], 1);
    }
    __syncthreads();

    // ---- inclusive Hillis-Steele scan over 512 (covers 424 buckets) ----
    for (int d = 1; d < 512; d <<= 1) {
        int v0 = s[tid]       + (tid >= d ? s[tid - d] : 0);
        int v1 = s[tid + 256] + (tid + 256 >= d ? s[tid + 256 - d] : 0);
        __syncthreads();
        s[tid] = v0; s[tid + 256] = v1;
        __syncthreads();
    }
    for (int i = tid; i < NKEY; i += BLK)                    // FIX: cover ALL 424 buckets
        cur[i] = (i == 0) ? 0 : s[i - 1];                    // exclusive starts
    __syncthreads();

    // ---- phase B: scatter (class<<16 | rowid) into (tile,warp)-bucketed order ----
    for (int i = tid; i < n; i += BLK) {
        int c = stgt[i];
        int key = (i >> 6) * NWARP + (c >> 3);
        int pos = atomicAdd(&cur[key], 1);
        scomb[pos] = (unsigned int)i | ((unsigned int)c << 16);
    }
    __syncthreads();

    // ---- phase C: sequential tile streaming; warp processes ONLY its bucket ----
    // warp w owns classes [8w,8w+8); lane l owns dims [4l,4l+4)
    float4 a0={0,0,0,0},a1={0,0,0,0},a2={0,0,0,0},a3={0,0,0,0};
    float4 a4={0,0,0,0},a5={0,0,0,0},a6={0,0,0,0},a7={0,0,0,0};
    float sq0 = 0.f, sq1 = 0.f;

    const float4* fbase = (const float4*)feat + (size_t)r0 * FD4;
    const int lim4 = n * FD4;
    const float4 Z = {0,0,0,0};
    float4 st[8];

    // prolog: load tile 0 (sequential, unconditional when full)
    if (lim4 >= T * FD4) {
#pragma unroll
        for (int i = 0; i < 8; i++) st[i] = fbase[tid + i * BLK];
    } else {
#pragma unroll
        for (int i = 0; i < 8; i++) { int idx = tid + i * BLK; st[i] = (idx < lim4) ? fbase[idx] : Z; }
    }

    for (int t = 0; t < NTa; t++) {
        // deposit + fp32 sumsq
#pragma unroll
        for (int i = 0; i < 8; i++) {
            tile4[tid + i * BLK] = st[i];
            float4 x = st[i];
            if (i & 1) sq1 = fmaf(x.x,x.x, fmaf(x.y,x.y, fmaf(x.z,x.z, fmaf(x.w,x.w, sq1))));
            else       sq0 = fmaf(x.x,x.x, fmaf(x.y,x.y, fmaf(x.z,x.z, fmaf(x.w,x.w, sq0))));
        }
        __syncthreads();

        // prefetch next tile (overlaps the bucket walk)
        if (t + 1 < NTa) {
            const int b4 = (t + 1) * (T * FD4);
            if (b4 + T * FD4 <= lim4) {
#pragma unroll
                for (int i = 0; i < 8; i++) st[i] = fbase[b4 + tid + i * BLK];
            } else {
#pragma unroll
                for (int i = 0; i < 8; i++) { int idx = b4 + tid + i * BLK; st[i] = (idx < lim4) ? fbase[idx] : Z; }
            }
        }

        // walk this warp's bucket for tile t (every iteration useful)
        const int key  = t * NWARP + w;
        const int pbeg = (key == 0) ? 0 : s[key - 1];
        const int pend = s[key];
        for (int p = pbeg; p < pend; p++) {
            unsigned int u = scomb[p];                 // LDS broadcast
            int c = (int)(u >> 16);
            float4 x = tile4[(u & 63u) * FD4 + l];     // conflict-free LDS.128
            switch (c & 7) {                           // warp-uniform
                case 0: a0.x+=x.x; a0.y+=x.y; a0.z+=x.z; a0.w+=x.w; break;
                case 1: a1.x+=x.x; a1.y+=x.y; a1.z+=x.z; a1.w+=x.w; break;
                case 2: a2.x+=x.x; a2.y+=x.y; a2.z+=x.z; a2.w+=x.w; break;
                case 3: a3.x+=x.x; a3.y+=x.y; a3.z+=x.z; a3.w+=x.w; break;
                case 4: a4.x+=x.x; a4.y+=x.y; a4.z+=x.z; a4.w+=x.w; break;
                case 5: a5.x+=x.x; a5.y+=x.y; a5.z+=x.z; a5.w+=x.w; break;
                case 6: a6.x+=x.x; a6.y+=x.y; a6.z+=x.z; a6.w+=x.w; break;
                case 7: a7.x+=x.x; a7.y+=x.y; a7.z+=x.z; a7.w+=x.w; break;
            }
        }
        __syncthreads();                               // walk done before tile overwrite
    }

    // ---- flush register accumulators: one atomic per (class,dim) per block ----
    {
        float* gp = g_sums + (w * 8) * FD + (l << 2);
#define FLUSH(A) { atomicAdd(gp+0,(A).x); atomicAdd(gp+1,(A).y); \
                   atomicAdd(gp+2,(A).z); atomicAdd(gp+3,(A).w); gp += FD; }
        FLUSH(a0) FLUSH(a1) FLUSH(a2) FLUSH(a3)
        FLUSH(a4) FLUSH(a5) FLUSH(a6) FLUSH(a7)
#undef FLUSH
    }
    if (tid < NUM_C) atomicAdd(&g_counts[tid], hist[tid]);

    float sq = sq0 + sq1;
#pragma unroll
    for (int o = 16; o > 0; o >>= 1) sq += __shfl_down_sync(0xffffffffu, sq, o);
    if (l == 0) s_sq[w] = sq;
    __syncthreads();
    if (tid == 0) {
        float tsum = 0.f;
#pragma unroll
        for (int k = 0; k < NWARP; k++) tsum += s_sq[k];
        atomicAdd(&g_sumsq, tsum);
    }

    __threadfence();
    __syncthreads();
    if (tid == 0) {
        unsigned int tk = atomicAdd(&g_ticket, 1u);
        s_last = (tk == gridDim.x - 1);
    }
    __syncthreads();
    if (!s_last) return;

    // ================= last block: epilogue (cent aliases tile) =================
    __threadfence();
    float* cent = tile;

    float ipart = 0.f;
    for (int i = tid; i < NUM_C * FD; i += BLK) {
        const int c = i >> 7;
        float cntc = fmaxf((float)g_counts[c], 1.0f);
        float sg = g_sums[i];
        float ce = sg / cntc;
        cent[i]  = ce;
        ipart   += sg * ce;                // sum_c cnt_c * ||cent_c||^2
        g_sums[i] = 0.f;                   // reset for next graph replay
    }
    float ssq = 0.f;
    if (tid == 0) { ssq = g_sumsq; g_sumsq = 0.f; g_ticket = 0u; }
    __syncthreads();
    if (tid < NUM_C) g_counts[tid] = 0;

#pragma unroll
    for (int o = 16; o > 0; o >>= 1) ipart += __shfl_down_sync(0xffffffffu, ipart, o);
    if (l == 0) s_red[w] = ipart;
    __syncthreads();

    const float4* c4 = (const float4*)cent;
    float hsum = 0.f;
    for (int i = w; i < NUM_C - 1; i += NWARP) {
        float4 a = c4[i * FD4 + l];
        for (int j = i + 1; j < NUM_C; j++) {
            float4 b = c4[j * FD4 + l];
            float dx = a.x - b.x, dy = a.y - b.y, dz = a.z - b.z, dw = a.w - b.w;
            float d2 = dx * dx + dy * dy + dz * dz + dw * dw;
#pragma unroll
            for (int o = 16; o > 0; o >>= 1) d2 += __shfl_down_sync(0xffffffffu, d2, o);
            if (l == 0) {
                float wt = (i == 1 && j == 2) ? 2.0f : 1.0f;
                hsum += wt * fmaxf(2.0f - d2, 0.0f);     // MARGIN = 2
            }
        }
    }
    if (l == 0) s_hred[w] = hsum;
    __syncthreads();

    if (tid == 0) {
        float isum = 0.f, hs = 0.f;
#pragma unroll
        for (int k = 0; k < NWARP; k++) { isum += s_red[k]; hs += s_hred[k]; }
        out[0] = (ssq - isum) / (float)B + hs / (float)N_PAIRS;
    }
}

extern "C" void kernel_launch(void* const* d_in, const int* in_sizes, int n_in,
                              void* d_out, int out_size) {
    const float* feat = (const float*)d_in[0];
    const int*   tgt  = (const int*)d_in[1];
    const int B = in_sizes[1];
    cudaFuncSetAttribute(fused_k, cudaFuncAttributeMaxDynamicSharedMemorySize, SMEM_DYN);
    fused_k<<<GRID, BLK, SMEM_DYN>>>(feat, tgt, B, (float*)d_out);
}